// round 5
// baseline (speedup 1.0000x reference)
#include <cuda_runtime.h>
#include <cstdint>

// Problem constants (fixed by setup_inputs)
#define EN 1000000       // total embedding rows
#define DN 128           // embedding dim
#define CN 262144        // cache rows
#define NN 16384         // number of ids
#define W_ALL 31250      // EN/32 bitmap words
#define W_C   8192       // CN/32
#define W_MISS (W_ALL - W_C)   // 23058 words covering rows [C, E)
#define NB 101           // buckets: key -1 -> 0, freq v -> v+1 (freq in [0,100))
#define WT 8192          // warps in counting-sort passes (1 slot per lane)
#define MS_CH 23         // missScan items per thread (1024*23 >= W_MISS)
#define MS_PAD (1024*MS_CH)
#define HIST_WORDS ((NB * WT) / 4)   // g_histB as words for clearing

// -------- scratch (no allocations allowed) --------
__device__ int g_is64;
__device__ unsigned int g_present[W_ALL];
__device__ unsigned int g_prot[W_C];
__device__ int g_missScan[W_MISS];
__device__ unsigned char g_histB[NB * WT];   // per-warp bucket counts (<=32 fits uchar)
__device__ int g_warpBase[NB * WT];          // exclusive scan across warps per bucket
__device__ int g_total[NB];
__device__ int g_slotAtRank[NN];

__device__ __forceinline__ long long ld_idx(const void* p, long long i) {
    if (g_is64) return ((const long long*)p)[i];
    return (long long)((const int*)p)[i];
}

// -------- K0: clear bitmaps + hist bytes + detect index width --------
__global__ void k_clear(const void* ids) {
    int i = blockIdx.x * blockDim.x + threadIdx.x;
    if (i < W_ALL) g_present[i] = 0u;
    if (i < W_C)   g_prot[i] = 0u;
    if (i < HIST_WORDS) ((unsigned int*)g_histB)[i] = 0u;
    if (i == 0) {
        const long long* p = (const long long*)ids;
        int ok = 1;
        #pragma unroll
        for (int k = 0; k < 8; k++) {
            long long v = p[k];
            if (v < 0 || v >= (long long)EN) ok = 0;
        }
        g_is64 = ok;
    }
}

// -------- K1: scatter presence + protected-slot bits --------
__global__ void k_scatter(const void* ids, const void* idx_map, const void* inv) {
    int i = blockIdx.x * blockDim.x + threadIdx.x;
    if (i >= NN) return;
    long long id  = ld_idx(ids, i);
    long long row = ld_idx(idx_map, id);
    atomicOr(&g_present[row >> 5], 1u << (row & 31));
    long long slot = ld_idx(inv, row);
    if (slot >= 0) atomicOr(&g_prot[slot >> 5], 1u << (slot & 31));
}

// -------- K2: popcount exclusive scan over words [W_C, W_ALL), one block --------
__global__ void k_missScan() {
    __shared__ unsigned char pc[MS_PAD];
    __shared__ int ws[32];
    int tid = threadIdx.x, lane = tid & 31, wid = tid >> 5;
    for (int i = tid; i < MS_PAD; i += 1024)
        pc[i] = (i < W_MISS) ? (unsigned char)__popc(g_present[W_C + i]) : 0;
    __syncthreads();
    int base = tid * MS_CH;
    int sum = 0;
    #pragma unroll
    for (int k = 0; k < MS_CH; k++) sum += pc[base + k];
    int x = sum;
    #pragma unroll
    for (int o = 1; o < 32; o <<= 1) {
        int y = __shfl_up_sync(0xffffffffu, x, o);
        if (lane >= o) x += y;
    }
    if (lane == 31) ws[wid] = x;
    __syncthreads();
    if (wid == 0) {
        int s = ws[lane];
        #pragma unroll
        for (int o = 1; o < 32; o <<= 1) {
            int y = __shfl_up_sync(0xffffffffu, s, o);
            if (lane >= o) s += y;
        }
        ws[lane] = s;
    }
    __syncthreads();
    int run = (wid ? ws[wid - 1] : 0) + x - sum;
    #pragma unroll
    for (int k = 0; k < MS_CH; k++) {
        int w = base + k;
        if (w < W_MISS) g_missScan[w] = run;
        run += pc[base + k];
    }
}

// key for slot s (one lane = one slot): protected -> NB (dropped),
// cached_row<0 -> 0, else freq+1 clamped to [1,100]
__device__ __forceinline__ int slot_key(const void* cached, const void* freq,
                                        int wg, int lane) {
    unsigned int pw = g_prot[wg];           // word index == wg (32 slots/word)
    int s = wg * 32 + lane;
    if ((pw >> lane) & 1u) return NB;
    long long c = ld_idx(cached, s);
    if (c < 0) return 0;
    long long cc = c >= EN ? EN - 1 : c;
    int f = (int)ld_idx(freq, cc);
    f = f < 0 ? 0 : (f > 99 ? 99 : f);
    return f + 1;
}

// -------- K3: per-warp bucket counts (stable counting sort, pass 1) --------
__global__ void k_hist(const void* cached, const void* freq) {
    int t = blockIdx.x * blockDim.x + threadIdx.x;
    int wg = t >> 5, lane = t & 31;
    int key = slot_key(cached, freq, wg, lane);
    unsigned int mask = __match_any_sync(0xffffffffu, key);
    if (key < NB && lane == (__ffs(mask) - 1))
        g_histB[key * WT + wg] = (unsigned char)__popc(mask);
}

// -------- K4: per-bucket exclusive scan across the 8192 warps --------
__global__ void k_scan() {
    __shared__ int ws[32];
    int v = blockIdx.x, t = threadIdx.x, lane = t & 31, wid = t >> 5;
    const unsigned char* hp = g_histB + v * WT;
    int base = t * 8;
    uchar4 a = *(const uchar4*)(hp + base);
    uchar4 b = *(const uchar4*)(hp + base + 4);
    int e[8] = {a.x, a.y, a.z, a.w, b.x, b.y, b.z, b.w};
    int sum = e[0] + e[1] + e[2] + e[3] + e[4] + e[5] + e[6] + e[7];
    int x = sum;
    #pragma unroll
    for (int o = 1; o < 32; o <<= 1) {
        int y = __shfl_up_sync(0xffffffffu, x, o);
        if (lane >= o) x += y;
    }
    if (lane == 31) ws[wid] = x;
    __syncthreads();
    if (wid == 0) {
        int s = ws[lane];
        #pragma unroll
        for (int o = 1; o < 32; o <<= 1) {
            int y = __shfl_up_sync(0xffffffffu, s, o);
            if (lane >= o) s += y;
        }
        ws[lane] = s;
    }
    __syncthreads();
    int run = (wid ? ws[wid - 1] : 0) + x - sum;
    int* tb = g_warpBase + v * WT + base;
    #pragma unroll
    for (int k = 0; k < 8; k++) { tb[k] = run; run += e[k]; }
    if (t == 1023) g_total[v] = run;
}

// -------- K5: placement — write first NN positions of the stable LFU order --------
__global__ void k_place(const void* cached, const void* freq) {
    __shared__ int vb[NB];
    int lane = threadIdx.x & 31, wid = threadIdx.x >> 5;
    if (wid == 0) {           // bucket-total exclusive scan (101 values)
        int run = 0;
        #pragma unroll
        for (int b = 0; b < NB; b += 32) {
            int idx = b + lane;
            int tv = (idx < NB) ? g_total[idx] : 0;
            int x = tv;
            #pragma unroll
            for (int o = 1; o < 32; o <<= 1) {
                int y = __shfl_up_sync(0xffffffffu, x, o);
                if (lane >= o) x += y;
            }
            if (idx < NB) vb[idx] = run + x - tv;
            run += __shfl_sync(0xffffffffu, x, 31);
        }
    }
    __syncthreads();
    int t = blockIdx.x * blockDim.x + threadIdx.x;
    int wg = t >> 5;
    int key = slot_key(cached, freq, wg, lane);
    unsigned int mask = __match_any_sync(0xffffffffu, key);
    if (key < NB) {
        int prefix = __popc(mask & ((1u << lane) - 1u));
        int pos = vb[key] + g_warpBase[key * WT + wg] + prefix;
        if (pos < NN) g_slotAtRank[pos] = wg * 32 + lane;
    }
}

// -------- K6: final gather — one warp per output row --------
// idxMode: 0 = no idx output, 1 = one float per idx, 2 = raw int64 (2 f32 slots)
__global__ void k_gather(const void* ids, const void* idx_map, const void* inv,
                         const float* __restrict__ weight, const float* __restrict__ cw,
                         float* outIdx, int idxMode, float* __restrict__ outVec) {
    int gt = blockIdx.x * blockDim.x + threadIdx.x;
    int i = gt >> 5;
    int lane = gt & 31;
    if (i >= NN) return;
    long long id   = ld_idx(ids, i);
    long long row  = ld_idx(idx_map, id);
    long long slot = ld_idx(inv, row);
    long long g;
    const float* src;
    if (slot >= 0) {
        g = slot;
        src = cw + (size_t)g * DN;
    } else {
        int w = (int)(row >> 5);
        unsigned int below = g_present[w] & ((1u << (row & 31)) - 1u);
        int rank = g_missScan[w - W_C] + __popc(below);
        g = g_slotAtRank[rank];
        src = weight + (size_t)row * DN;   // write-back never touches rows >= C
    }
    if (lane == 0) {
        if (idxMode == 1) outIdx[i] = (float)g;
        else if (idxMode == 2) ((long long*)outIdx)[i] = g;
    }
    float4* dst = (float4*)(outVec + (size_t)i * DN);
    dst[lane] = ((const float4*)src)[lane];
}

extern "C" void kernel_launch(void* const* d_in, const int* in_sizes, int n_in,
                              void* d_out, int out_size) {
    const void* ids     = d_in[0];
    const void* idx_map = d_in[1];
    const void* cached  = d_in[2];
    const void* inv     = d_in[3];
    const void* freq    = d_in[4];
    const float* weight = (const float*)d_in[5];
    const float* cw     = (const float*)d_in[6];

    int clearN = HIST_WORDS > W_ALL ? HIST_WORDS : W_ALL;
    k_clear   <<<(clearN + 255) / 256, 256>>>(ids);
    k_scatter <<<(NN + 255) / 256, 256>>>(ids, idx_map, inv);
    k_missScan<<<1, 1024>>>();
    k_hist    <<<(WT * 32) / 256, 256>>>(cached, freq);
    k_scan    <<<NB, 1024>>>();
    k_place   <<<(WT * 32) / 256, 256>>>(cached, freq);

    float* outIdx = nullptr;
    float* outVec = (float*)d_out;
    int idxMode = 0;
    long long total = (long long)out_size;
    if (total >= (long long)NN * DN + 2 * NN) {
        outIdx = (float*)d_out;
        outVec = (float*)d_out + 2 * NN;
        idxMode = 2;
    } else if (total >= (long long)NN * DN + NN) {
        outIdx = (float*)d_out;
        outVec = (float*)d_out + NN;
        idxMode = 1;
    }
    k_gather  <<<(NN * 32 + 255) / 256, 256>>>(ids, idx_map, inv, weight, cw,
                                               outIdx, idxMode, outVec);
}